// round 8
// baseline (speedup 1.0000x reference)
#include <cuda_runtime.h>
#include <cstdint>

#define T_STEPS 32
#define BATCH   8
#define NT      256
#define CIN_    1024
#define DCH     512
#define KC      64
#define PIX     196
#define NJ      (NT * PIX)        // 50176 pixel rows

// ---------------- scratch (device globals; no allocations) ----------------
__device__ float g_xhi[NJ * CIN_];           // tf32-hi of x, (j, c)
__device__ float g_xlo[NJ * CIN_];           // residual lo
__device__ float g_whi[DCH * CIN_];
__device__ float g_wlo[DCH * CIN_];
__device__ float g_xrt[NJ * DCH];            // xr transposed: (j, d)
__device__ float g_wxb[NT * KC * PIX];       // (n, k, p)
__device__ float g_h[2 * BATCH * KC * PIX];
__device__ float g_rh[2 * BATCH * KC * PIX];
__device__ float g_fwd[NT * KC * PIX];
__device__ float g_bwd[NT * KC * PIX];
__device__ float g_assign[NT * KC * PIX];
__device__ float g_asum[NT * KC];
__device__ float g_vlad[BATCH * KC * DCH];
__device__ unsigned int g_barrier[16];

static __device__ __forceinline__ float sigf(float v) { return 1.0f / (1.0f + expf(-v)); }

__device__ __forceinline__ uint32_t smem_to_u32(const void* p) {
    uint32_t a;
    asm("{ .reg .u64 t; cvta.to.shared.u64 t, %1; cvt.u32.u64 %0, t; }" : "=r"(a) : "l"(p));
    return a;
}

// cp.async 16B
__device__ __forceinline__ void cp16(uint32_t saddr, const float* g) {
    asm volatile("cp.async.cg.shared.global [%0], [%1], 16;"
                 :: "r"(saddr), "l"(__cvta_generic_to_global((const void*)g)) : "memory");
}
#define CP_COMMIT() asm volatile("cp.async.commit_group;" ::: "memory")
#define CP_WAIT1()  asm volatile("cp.async.wait_group 1;" ::: "memory")
#define CP_WAIT0()  asm volatile("cp.async.wait_group 0;" ::: "memory")

// m16n8k8 tf32 mma (legacy path, compiles under compute_100)
#define MMA_TF32(c, a, b0_, b1_) \
    asm volatile("mma.sync.aligned.m16n8k8.row.col.f32.tf32.tf32.f32 " \
        "{%0,%1,%2,%3}, {%4,%5,%6,%7}, {%8,%9}, {%0,%1,%2,%3};" \
        : "+f"((c)[0]), "+f"((c)[1]), "+f"((c)[2]), "+f"((c)[3]) \
        : "r"((a)[0]), "r"((a)[1]), "r"((a)[2]), "r"((a)[3]), "r"(b0_), "r"(b1_))

// packed fp32x2 helpers
static __device__ __forceinline__ unsigned long long pack2(float v) {
    unsigned long long r;
    unsigned u = __float_as_uint(v);
    asm("mov.b64 %0, {%1, %1};" : "=l"(r) : "r"(u));
    return r;
}
static __device__ __forceinline__ void ffma2(unsigned long long& d,
                                             unsigned long long a,
                                             unsigned long long b) {
    asm volatile("fma.rn.f32x2 %0, %1, %2, %0;" : "+l"(d) : "l"(a), "l"(b));
}

// ---------------- init ----------------
__global__ void init_kernel()
{
    int i = blockIdx.x * 256 + threadIdx.x;
    if (i < 2 * BATCH * KC * PIX) g_h[i] = 0.0f;
    if (i < BATCH * KC * DCH)     g_vlad[i] = 0.0f;
    if (i < 16)                   g_barrier[i] = 0u;
}

// ---------------- transpose + tf32 split: X (n,c,p) -> Xt_hi/lo (j=n*196+p, c) ----------------
// 32-channel tile: 32*197*4 = 25216 B static smem (under 48KB static cap)
__global__ void __launch_bounds__(256) transpose_split(const float* __restrict__ X)
{
    __shared__ float ts[32][197];
    const int n = blockIdx.x, c0 = blockIdx.y * 32;
    for (int i = threadIdx.x; i < 32 * 196; i += 256) {
        int c = i / 196, p = i - c * 196;
        ts[c][p] = X[((size_t)n * CIN_ + c0 + c) * PIX + p];
    }
    __syncthreads();
    for (int i = threadIdx.x; i < 196 * 32; i += 256) {
        int p = i >> 5, c = i & 31;
        float v = ts[c][p];
        uint32_t hb; asm("cvt.rna.tf32.f32 %0, %1;" : "=r"(hb) : "f"(v));
        float hf = __uint_as_float(hb);
        size_t o = ((size_t)n * PIX + p) * CIN_ + c0 + c;
        g_xhi[o] = hf;
        g_xlo[o] = v - hf;
    }
}

// ---------------- weight tf32 split ----------------
__global__ void wsplit_kernel(const float* __restrict__ W)
{
    int i = blockIdx.x * 256 + threadIdx.x;
    if (i < DCH * CIN_) {
        float v = W[i];
        uint32_t hb; asm("cvt.rna.tf32.f32 %0, %1;" : "=r"(hb) : "f"(v));
        float hf = __uint_as_float(hb);
        g_whi[i] = hf;
        g_wlo[i] = v - hf;
    }
}

// ---------------- conv1: TF32x3 GEMM via mma.sync (m16n8k8) ----------------
// xrT[j, d] = bias[d] + sum_c x[j,c] * W[d,c]
// Block tile: 128 (j) x 128 (d), 8 warps as 2x4, warp tile 64x32.
// Pass 0 (64 iters): A = x_hi, B = {W_hi, W_lo}; Pass 1: A = x_lo, B = W_hi.
// SMEM (dynamic, 61440B): A[2][128][20] | B0[2][128][20] | B1[2][128][20]
#define C1_SMEM 61440
__global__ void __launch_bounds__(256)
conv1_mma(const float* __restrict__ bias)
{
    extern __shared__ char smc[];
    const uint32_t sbase = smem_to_u32(smc);
    const int tid  = threadIdx.x;
    const int wid  = tid >> 5, lane = tid & 31;
    const int d0   = blockIdx.x * 128;
    const int j0   = blockIdx.y * 128;
    const int wm   = wid & 1, wn = wid >> 1;
    const int g    = lane >> 2, tg = lane & 3;

    float c[4][4][4];
#pragma unroll
    for (int mt = 0; mt < 4; mt++)
#pragma unroll
        for (int nt = 0; nt < 4; nt++)
#pragma unroll
            for (int q = 0; q < 4; q++) c[mt][nt][q] = 0.0f;

    const int rr = tid >> 2, c4 = tid & 3;

    auto issue = [&](int i) {
        const int pass = i >> 6, kk = (i & 63) * 16, buf = i & 1;
        const float* Asrc = pass ? g_xlo : g_xhi;
#pragma unroll
        for (int q = 0; q < 2; q++) {
            int r = rr + q * 64;
            uint32_t so = (uint32_t)(r * 80 + c4 * 16);
            size_t goA = (size_t)(j0 + r) * CIN_ + kk + c4 * 4;
            size_t goW = (size_t)(d0 + r) * CIN_ + kk + c4 * 4;
            cp16(sbase + buf * 10240 + so,         Asrc + goA);
            cp16(sbase + 20480 + buf * 10240 + so, g_whi + goW);
            if (pass == 0)
                cp16(sbase + 40960 + buf * 10240 + so, g_wlo + goW);
        }
        CP_COMMIT();
    };

    issue(0);
    for (int i = 0; i < 128; i++) {
        if (i < 127) { issue(i + 1); CP_WAIT1(); }
        else         { CP_WAIT0(); }
        __syncthreads();

        const int buf = i & 1, pass = i >> 6;
        const char* ab  = smc + buf * 10240;
        const char* b0b = smc + 20480 + buf * 10240;
        const char* b1b = smc + 40960 + buf * 10240;

#pragma unroll
        for (int ks = 0; ks < 2; ks++) {
            const int kb = ks * 8 + tg;
            uint32_t a[4][4];
#pragma unroll
            for (int mt = 0; mt < 4; mt++) {
                int m = wm * 64 + mt * 16 + g;
                const float* pa0 = (const float*)(ab + m * 80);
                const float* pa1 = pa0 + 8 * 20;
                a[mt][0] = __float_as_uint(pa0[kb]);
                a[mt][1] = __float_as_uint(pa1[kb]);
                a[mt][2] = __float_as_uint(pa0[kb + 4]);
                a[mt][3] = __float_as_uint(pa1[kb + 4]);
            }
#pragma unroll
            for (int nt = 0; nt < 4; nt++) {
                int n = wn * 32 + nt * 8 + g;
                const float* pb = (const float*)(b0b + n * 80);
                uint32_t b0 = __float_as_uint(pb[kb]);
                uint32_t b1 = __float_as_uint(pb[kb + 4]);
#pragma unroll
                for (int mt = 0; mt < 4; mt++) MMA_TF32(c[mt][nt], a[mt], b0, b1);
                if (pass == 0) {
                    const float* pc = (const float*)(b1b + n * 80);
                    uint32_t e0 = __float_as_uint(pc[kb]);
                    uint32_t e1 = __float_as_uint(pc[kb + 4]);
#pragma unroll
                    for (int mt = 0; mt < 4; mt++) MMA_TF32(c[mt][nt], a[mt], e0, e1);
                }
            }
        }
        __syncthreads();
    }

    // epilogue: add bias, store xrT[j][d] (float2)
#pragma unroll
    for (int mt = 0; mt < 4; mt++) {
        int r0 = j0 + wm * 64 + mt * 16 + g;
#pragma unroll
        for (int nt = 0; nt < 4; nt++) {
            int col = d0 + wn * 32 + nt * 8 + tg * 2;
            float2 bv = *(const float2*)&bias[col];
            float2 v0, v1;
            v0.x = c[mt][nt][0] + bv.x; v0.y = c[mt][nt][1] + bv.y;
            v1.x = c[mt][nt][2] + bv.x; v1.y = c[mt][nt][3] + bv.y;
            *(float2*)&g_xrt[(size_t)r0 * DCH + col]       = v0;
            *(float2*)&g_xrt[(size_t)(r0 + 8) * DCH + col] = v1;
        }
    }
}

// ---------------- conv2: FFMA GEMM on xrT -> wxb (n,k,p) ----------------
__global__ void __launch_bounds__(256)
conv2_db(const float* __restrict__ SW, const float* __restrict__ SB, float* __restrict__ out)
{
    constexpr int BK = 16, BN = 128, TM = 4, TN = 8;
    __shared__ __align__(16) float As[2][BK][64];
    __shared__ __align__(16) float Bs[2][BK][BN];
    __shared__ int obase[BN];

    const int tid = threadIdx.x;
    if (tid < BN) {
        int jg = blockIdx.x * BN + tid;
        int n = jg / PIX, p = jg - n * PIX;
        obase[tid] = n * KC * PIX + p;
    }
    __syncthreads();

    const int tx = tid & 15, ty = tid >> 4;
    const int bj = tid & 127, bk = tid >> 7;
    const int jg = blockIdx.x * BN + bj;

    float4 areg, brga, brgb;

    auto loadA = [&](int k0) {
        int r = tid >> 2, c4 = tid & 3;
        areg = *(const float4*)&SW[r * DCH + k0 + c4 * 4];
    };
    auto loadB = [&](int k0) {
        const float* src = &g_xrt[(size_t)jg * DCH + k0 + bk * 8];
        brga = *(const float4*)&src[0];
        brgb = *(const float4*)&src[4];
    };
    auto storeA = [&](int buf) {
        int r = tid >> 2, c4 = tid & 3;
        As[buf][c4 * 4 + 0][r] = areg.x;
        As[buf][c4 * 4 + 1][r] = areg.y;
        As[buf][c4 * 4 + 2][r] = areg.z;
        As[buf][c4 * 4 + 3][r] = areg.w;
    };
    auto storeB = [&](int buf) {
        Bs[buf][bk * 8 + 0][bj] = brga.x;
        Bs[buf][bk * 8 + 1][bj] = brga.y;
        Bs[buf][bk * 8 + 2][bj] = brga.z;
        Bs[buf][bk * 8 + 3][bj] = brga.w;
        Bs[buf][bk * 8 + 4][bj] = brgb.x;
        Bs[buf][bk * 8 + 5][bj] = brgb.y;
        Bs[buf][bk * 8 + 6][bj] = brgb.z;
        Bs[buf][bk * 8 + 7][bj] = brgb.w;
    };

    unsigned long long acc2[TM / 2][TN];
#pragma unroll
    for (int i = 0; i < TM / 2; i++)
#pragma unroll
        for (int j = 0; j < TN; j++) acc2[i][j] = 0ull;

    loadA(0); loadB(0);
    storeA(0); storeB(0);
    __syncthreads();

    int buf = 0;
    for (int k0 = 0; k0 < DCH; k0 += BK) {
        const bool more = (k0 + BK) < DCH;
        if (more) { loadA(k0 + BK); loadB(k0 + BK); }
#pragma unroll
        for (int kk = 0; kk < BK; kk++) {
            unsigned long long a2[TM / 2];
            ulonglong2 av = *(const ulonglong2*)&As[buf][kk][ty * TM];
            a2[0] = av.x; a2[1] = av.y;
            float4 b0 = *(const float4*)&Bs[buf][kk][tx * TN];
            float4 b1 = *(const float4*)&Bs[buf][kk][tx * TN + 4];
            unsigned long long bb[8];
            bb[0] = pack2(b0.x); bb[1] = pack2(b0.y); bb[2] = pack2(b0.z); bb[3] = pack2(b0.w);
            bb[4] = pack2(b1.x); bb[5] = pack2(b1.y); bb[6] = pack2(b1.z); bb[7] = pack2(b1.w);
#pragma unroll
            for (int i = 0; i < TM / 2; i++)
#pragma unroll
                for (int j = 0; j < TN; j++) ffma2(acc2[i][j], a2[i], bb[j]);
        }
        if (more) {
            storeA(buf ^ 1); storeB(buf ^ 1);
            __syncthreads();
            buf ^= 1;
        }
    }

#pragma unroll
    for (int i = 0; i < TM / 2; i++) {
        int d0 = ty * TM + 2 * i;
        float bv0 = SB[d0], bv1 = SB[d0 + 1];
#pragma unroll
        for (int j = 0; j < TN; j++) {
            unsigned long long u = acc2[i][j];
            float lo = __uint_as_float((unsigned)u);
            float hi = __uint_as_float((unsigned)(u >> 32));
            int o = obase[tx * TN + j];
            out[o + d0 * PIX]       = lo + bv0;
            out[o + (d0 + 1) * PIX] = hi + bv1;
        }
    }
}

// ---------------- persistent bidirectional GRU ----------------
#define GRU_THREADS 448
#define HS_FLOATS   (64 * 272)
#define WS_FLOATS   4608
#define PP_FLOATS   1568
#define GRU_SMEM_FLOATS (HS_FLOATS + 3 * WS_FLOATS + 2 * PP_FLOATS)

__global__ void __launch_bounds__(GRU_THREADS, 1)
gru_persistent(const float* __restrict__ Uz, const float* __restrict__ Ur,
               const float* __restrict__ Uh)
{
    extern __shared__ float sm[];
    float* hs = sm;
    float* wz = sm + HS_FLOATS;
    float* wr = wz + WS_FLOATS;
    float* wh = wr + WS_FLOATS;
    float* p0 = wh + WS_FLOATS;
    float* p1 = p0 + PP_FLOATS;

    const int blk = blockIdx.x;
    const int grp = blk >> 3;
    const int kg  = blk & 7;
    const int dir = grp >> 3;
    const int b   = grp & 7;
    const int tid = threadIdx.x;

    const int ko0 = kg * 8;
    for (int i = tid; i < WS_FLOATS; i += GRU_THREADS) {
        wz[i] = Uz[ko0 * 576 + i];
        wr[i] = Ur[ko0 * 576 + i];
        wh[i] = Uh[ko0 * 576 + i];
    }
    for (int i = tid; i < HS_FLOATS; i += GRU_THREADS) hs[i] = 0.0f;

    const int half  = tid / 224;
    const int lt    = tid - half * 224;
    const int ko_l  = lt / 28;
    const int g28   = lt - ko_l * 28;
    const int row   = g28 >> 1, xh = (g28 & 1) * 7;
    const int ko    = ko0 + ko_l;
    const int ci0   = half * 32;
    const int pbase = row * 14 + xh;
    const int pidx  = ko_l * PIX + pbase;

    float* hstate = g_h  + grp * KC * PIX;
    float* rhbuf  = g_rh + grp * KC * PIX;
    float* gdst   = (dir == 0) ? g_fwd : g_bwd;

    unsigned bar_target = 0;
    float zreg[7], hold[7];

    for (int s = 0; s < T_STEPS; s++) {
        const int t = dir ? (31 - s) : s;
        const int n = b * 32 + t;
        const float* wt = g_wxb + (n * KC + ko) * PIX + pbase;

        for (int i = tid; i < KC * PIX; i += GRU_THREADS) {
            int ci = i / PIX, p = i - ci * PIX;
            int y = p / 14, x = p - y * 14;
            hs[ci * 272 + (y + 1) * 17 + (x + 1)] = __ldcg(&hstate[i]);
        }
        __syncthreads();

        float az[7], ar[7];
#pragma unroll
        for (int i = 0; i < 7; i++) { az[i] = 0.0f; ar[i] = 0.0f; }
        {
            const float* wzb = wz + ko_l * 576 + ci0 * 9;
            const float* wrb = wr + ko_l * 576 + ci0 * 9;
            const float* hb  = hs + ci0 * 272 + row * 17 + xh;
#pragma unroll 1
            for (int ci = 0; ci < 32; ci++) {
                const float* hp = hb + ci * 272;
                float r0[9], r1[9], r2[9];
#pragma unroll
                for (int i = 0; i < 9; i++) { r0[i] = hp[i]; r1[i] = hp[17 + i]; r2[i] = hp[34 + i]; }
                const float* wz9 = wzb + ci * 9;
                const float* wr9 = wrb + ci * 9;
                float z0=wz9[0],z1=wz9[1],z2=wz9[2],z3=wz9[3],z4=wz9[4],z5=wz9[5],z6=wz9[6],z7=wz9[7],z8=wz9[8];
                float q0=wr9[0],q1=wr9[1],q2=wr9[2],q3=wr9[3],q4=wr9[4],q5=wr9[5],q6=wr9[6],q7=wr9[7],q8=wr9[8];
#pragma unroll
                for (int px = 0; px < 7; px++) {
                    az[px] += z0*r0[px] + z1*r0[px+1] + z2*r0[px+2]
                            + z3*r1[px] + z4*r1[px+1] + z5*r1[px+2]
                            + z6*r2[px] + z7*r2[px+1] + z8*r2[px+2];
                    ar[px] += q0*r0[px] + q1*r0[px+1] + q2*r0[px+2]
                            + q3*r1[px] + q4*r1[px+1] + q5*r1[px+2]
                            + q6*r2[px] + q7*r2[px+1] + q8*r2[px+2];
                }
            }
        }
        if (half == 1) {
#pragma unroll
            for (int px = 0; px < 7; px++) { p0[pidx + px] = az[px]; p1[pidx + px] = ar[px]; }
        }
        __syncthreads();
        if (half == 0) {
            const float* hko = hs + ko * 272 + (row + 1) * 17 + (xh + 1);
#pragma unroll
            for (int px = 0; px < 7; px++) {
                float w = wt[px];
                float z = sigf(w + az[px] + p0[pidx + px]);
                float r = sigf(w + ar[px] + p1[pidx + px]);
                float h0 = hko[px];
                zreg[px] = z;
                hold[px] = h0;
                rhbuf[ko * PIX + pbase + px] = r * h0;
            }
        }

        __threadfence();
        __syncthreads();
        bar_target += 8;
        if (tid == 0) {
            atomicAdd(&g_barrier[grp], 1u);
            while (*((volatile unsigned int*)&g_barrier[grp]) < bar_target) __nanosleep(64);
            __threadfence();
        }
        __syncthreads();

        for (int i = tid; i < KC * PIX; i += GRU_THREADS) {
            int ci = i / PIX, p = i - ci * PIX;
            int y = p / 14, x = p - y * 14;
            hs[ci * 272 + (y + 1) * 17 + (x + 1)] = __ldcg(&rhbuf[i]);
        }
        __syncthreads();

        float ah[7];
#pragma unroll
        for (int i = 0; i < 7; i++) ah[i] = 0.0f;
        {
            const float* whb = wh + ko_l * 576 + ci0 * 9;
            const float* hb  = hs + ci0 * 272 + row * 17 + xh;
#pragma unroll 1
            for (int ci = 0; ci < 32; ci++) {
                const float* hp = hb + ci * 272;
                float r0[9], r1[9], r2[9];
#pragma unroll
                for (int i = 0; i < 9; i++) { r0[i] = hp[i]; r1[i] = hp[17 + i]; r2[i] = hp[34 + i]; }
                const float* w9 = whb + ci * 9;
                float w0=w9[0],w1=w9[1],w2=w9[2],w3=w9[3],w4=w9[4],w5=w9[5],w6=w9[6],w7=w9[7],w8=w9[8];
#pragma unroll
                for (int px = 0; px < 7; px++) {
                    ah[px] += w0*r0[px] + w1*r0[px+1] + w2*r0[px+2]
                            + w3*r1[px] + w4*r1[px+1] + w5*r1[px+2]
                            + w6*r2[px] + w7*r2[px+1] + w8*r2[px+2];
                }
            }
        }
        if (half == 1) {
#pragma unroll
            for (int px = 0; px < 7; px++) p0[pidx + px] = ah[px];
        }
        __syncthreads();
        if (half == 0) {
            float* hdst = hstate + ko * PIX + pbase;
            float* fdst = gdst + (n * KC + ko) * PIX + pbase;
#pragma unroll
            for (int px = 0; px < 7; px++) {
                float hh = tanhf(wt[px] + ah[px] + p0[pidx + px]);
                float z  = zreg[px];
                float hn = (1.0f - z) * hh + z * hold[px];
                hdst[px] = hn;
                fdst[px] = hn;
            }
        }

        __threadfence();
        __syncthreads();
        bar_target += 8;
        if (tid == 0) {
            atomicAdd(&g_barrier[grp], 1u);
            while (*((volatile unsigned int*)&g_barrier[grp]) < bar_target) __nanosleep(64);
            __threadfence();
        }
        __syncthreads();
    }
}

// ---------------- softmax over K per pixel + per-(n,k) pixel sums ----------------
__global__ void softmax_kernel()
{
    const int n = blockIdx.x;
    const int p = threadIdx.x;
    const bool act = p < PIX;
    __shared__ float asum_s[KC];
    if (p < KC) asum_s[p] = 0.0f;
    __syncthreads();

    const float* f  = g_fwd + n * KC * PIX + p;
    const float* bd = g_bwd + n * KC * PIX + p;
    float m = -1e30f;
    if (act) {
        for (int k = 0; k < KC; k++) m = fmaxf(m, f[k * PIX] + bd[k * PIX]);
    }
    float ssum = 0.0f;
    if (act) {
        for (int k = 0; k < KC; k++) ssum += expf(f[k * PIX] + bd[k * PIX] - m);
    }
    const float inv = act ? (1.0f / ssum) : 0.0f;
    float* A = g_assign + n * KC * PIX + p;
    for (int k = 0; k < KC; k++) {
        float e = act ? expf(f[k * PIX] + bd[k * PIX] - m) * inv : 0.0f;
        if (act) A[k * PIX] = e;
        float es = e;
#pragma unroll
        for (int off = 16; off; off >>= 1) es += __shfl_down_sync(0xffffffffu, es, off);
        if ((p & 31) == 0) atomicAdd(&asum_s[k], es);
    }
    __syncthreads();
    if (p < KC) g_asum[n * KC + p] = asum_s[p];
}

// ---------------- VLAD einsum (B side reads xrT) ----------------
__global__ void vlad_gemm_kernel()
{
    __shared__ float As[14][65];
    __shared__ float Bs[14][65];
    const int b = blockIdx.y, d0 = blockIdx.x * 64, ch = blockIdx.z;
    const int tid = threadIdx.x;
    const int tx = tid & 15, ty = tid >> 4;

    float acc[4][4];
#pragma unroll
    for (int i = 0; i < 4; i++)
#pragma unroll
        for (int j = 0; j < 4; j++) acc[i][j] = 0.0f;

    for (int f = 0; f < 4; f++) {
        int n = b * 32 + ch * 4 + f;
        const float* Ap = g_assign + n * KC * PIX;
        const float* Xp = g_xrt + (size_t)n * PIX * DCH;
        for (int p0 = 0; p0 < PIX; p0 += 14) {
            for (int i = tid; i < 896; i += 256) {
                int r = i / 14, pp = i - r * 14;
                As[pp][r] = Ap[r * PIX + p0 + pp];
            }
            for (int i = tid; i < 896; i += 256) {
                int pp = i >> 6, r = i & 63;
                Bs[pp][r] = Xp[(size_t)(p0 + pp) * DCH + d0 + r];
            }
            __syncthreads();
#pragma unroll
            for (int pp = 0; pp < 14; pp++) {
                float a[4], x[4];
#pragma unroll
                for (int i = 0; i < 4; i++) a[i] = As[pp][ty * 4 + i];
#pragma unroll
                for (int j = 0; j < 4; j++) x[j] = Bs[pp][tx * 4 + j];
#pragma unroll
                for (int i = 0; i < 4; i++)
#pragma unroll
                    for (int j = 0; j < 4; j++) acc[i][j] += a[i] * x[j];
            }
            __syncthreads();
        }
    }
#pragma unroll
    for (int i = 0; i < 4; i++)
#pragma unroll
        for (int j = 0; j < 4; j++)
            atomicAdd(&g_vlad[(b * KC + ty * 4 + i) * DCH + d0 + tx * 4 + j], acc[i][j]);
}

// ---------------- subtract a-term + intra-row L2 normalize ----------------
__global__ void rownorm_kernel(const float* __restrict__ centers, float* __restrict__ out)
{
    const int k = blockIdx.x, b = blockIdx.y;
    const int tid = threadIdx.x;
    __shared__ float sred[128];
    __shared__ float s_sh;

    if (tid < 32) {
        float s = g_asum[(b * 32 + tid) * KC + k];
#pragma unroll
        for (int off = 16; off; off >>= 1) s += __shfl_down_sync(0xffffffffu, s, off);
        if (tid == 0) s_sh = s;
    }
    __syncthreads();
    const float s = s_sh;

    float v[4];
    float ssq = 0.0f;
#pragma unroll
    for (int j = 0; j < 4; j++) {
        int d = j * 128 + tid;
        v[j] = g_vlad[(b * KC + k) * DCH + d] - s * centers[k * DCH + d];
        ssq += v[j] * v[j];
    }
    sred[tid] = ssq;
    __syncthreads();
    for (int off = 64; off; off >>= 1) {
        if (tid < off) sred[tid] += sred[tid + off];
        __syncthreads();
    }
    const float scale = 1.0f / fmaxf(sqrtf(sred[0]), 1e-12f);
#pragma unroll
    for (int j = 0; j < 4; j++)
        out[b * KC * DCH + k * DCH + j * 128 + tid] = v[j] * scale;
}

// ---------------- final per-batch L2 normalize ----------------
__global__ void bnorm_kernel(float* __restrict__ out)
{
    const int b = blockIdx.x;
    const int tid = threadIdx.x;
    __shared__ float sred[256];
    float* o = out + b * KC * DCH;
    float ssq = 0.0f;
    for (int i = tid; i < KC * DCH; i += 256) { float v = o[i]; ssq += v * v; }
    sred[tid] = ssq;
    __syncthreads();
    for (int off = 128; off; off >>= 1) {
        if (tid < off) sred[tid] += sred[tid + off];
        __syncthreads();
    }
    const float scale = 1.0f / fmaxf(sqrtf(sred[0]), 1e-12f);
    for (int i = tid; i < KC * DCH; i += 256) o[i] *= scale;
}

// ---------------- host launcher ----------------
extern "C" void kernel_launch(void* const* d_in, const int* in_sizes, int n_in,
                              void* d_out, int out_size)
{
    const float* x       = (const float*)d_in[0];
    const float* redu_w  = (const float*)d_in[1];
    const float* redu_b  = (const float*)d_in[2];
    const float* share_w = (const float*)d_in[3];
    const float* share_b = (const float*)d_in[4];
    const float* U_z     = (const float*)d_in[5];
    const float* U_r     = (const float*)d_in[6];
    const float* U_h     = (const float*)d_in[7];
    const float* centers = (const float*)d_in[8];
    float* out = (float*)d_out;

    const int GRU_SMEM = GRU_SMEM_FLOATS * 4;
    cudaFuncSetAttribute(gru_persistent, cudaFuncAttributeMaxDynamicSharedMemorySize, GRU_SMEM);
    cudaFuncSetAttribute(conv1_mma, cudaFuncAttributeMaxDynamicSharedMemorySize, C1_SMEM);

    void* wxb_p; cudaGetSymbolAddress(&wxb_p, g_wxb);

    init_kernel<<<1024, 256>>>();

    // transpose + tf32 split of x, and of redu_w
    transpose_split<<<dim3(NT, CIN_ / 32), 256>>>(x);
    wsplit_kernel<<<(DCH * CIN_ + 255) / 256, 256>>>(redu_w);

    // conv1: TF32x3 GEMM via mma.sync -> xrT (j, d)
    conv1_mma<<<dim3(DCH / 128, NJ / 128), 256, C1_SMEM>>>(redu_b);

    // conv2: FFMA GEMM (64 x 512) on xrT -> wxb (n,k,p)
    conv2_db<<<NJ / 128, 256>>>(share_w, share_b, (float*)wxb_p);

    // persistent bidirectional GRU
    gru_persistent<<<128, GRU_THREADS, GRU_SMEM>>>(U_z, U_r, U_h);

    softmax_kernel<<<NT, 224>>>();
    vlad_gemm_kernel<<<dim3(8, BATCH, 8), 256>>>();
    rownorm_kernel<<<dim3(KC, BATCH), 128>>>(centers, out);
    bnorm_kernel<<<BATCH, 256>>>(out);
}

// round 9
// speedup vs baseline: 1.0137x; 1.0137x over previous
#include <cuda_runtime.h>
#include <cstdint>

#define T_STEPS 32
#define BATCH   8
#define NT      256
#define CIN_    1024
#define DCH     512
#define KC      64
#define PIX     196
#define NJ      (NT * PIX)        // 50176 pixel rows

// ---------------- scratch (device globals; no allocations) ----------------
__device__ float g_xhi[NJ * CIN_];           // tf32-hi of x, (j, c)
__device__ float g_xlo[NJ * CIN_];           // residual lo
__device__ float g_whi[DCH * CIN_];
__device__ float g_wlo[DCH * CIN_];
__device__ float g_xrt[NJ * DCH];            // xr transposed: (j, d)
__device__ float g_wxb[NT * KC * PIX];       // (n, k, p)
__device__ float g_h[2 * BATCH * KC * PIX];
__device__ float g_rh[2 * BATCH * KC * PIX];
__device__ float g_fwd[NT * KC * PIX];
__device__ float g_bwd[NT * KC * PIX];
__device__ float g_assign[NT * KC * PIX];
__device__ float g_asum[NT * KC];
__device__ float g_vlad[BATCH * KC * DCH];
__device__ unsigned int g_barrier[16];

static __device__ __forceinline__ float sigf(float v) { return 1.0f / (1.0f + expf(-v)); }

__device__ __forceinline__ uint32_t smem_to_u32(const void* p) {
    uint32_t a;
    asm("{ .reg .u64 t; cvta.to.shared.u64 t, %1; cvt.u32.u64 %0, t; }" : "=r"(a) : "l"(p));
    return a;
}

// cp.async 16B
__device__ __forceinline__ void cp16(uint32_t saddr, const float* g) {
    asm volatile("cp.async.cg.shared.global [%0], [%1], 16;"
                 :: "r"(saddr), "l"(__cvta_generic_to_global((const void*)g)) : "memory");
}
#define CP_COMMIT() asm volatile("cp.async.commit_group;" ::: "memory")
#define CP_WAIT1()  asm volatile("cp.async.wait_group 1;" ::: "memory")
#define CP_WAIT0()  asm volatile("cp.async.wait_group 0;" ::: "memory")

// m16n8k8 tf32 mma (legacy path, compiles under compute_100)
#define MMA_TF32(c, a, b0_, b1_) \
    asm volatile("mma.sync.aligned.m16n8k8.row.col.f32.tf32.tf32.f32 " \
        "{%0,%1,%2,%3}, {%4,%5,%6,%7}, {%8,%9}, {%0,%1,%2,%3};" \
        : "+f"((c)[0]), "+f"((c)[1]), "+f"((c)[2]), "+f"((c)[3]) \
        : "r"((a)[0]), "r"((a)[1]), "r"((a)[2]), "r"((a)[3]), "r"(b0_), "r"(b1_))

// packed fp32x2 helpers
static __device__ __forceinline__ unsigned long long pack2(float v) {
    unsigned long long r;
    unsigned u = __float_as_uint(v);
    asm("mov.b64 %0, {%1, %1};" : "=l"(r) : "r"(u));
    return r;
}
static __device__ __forceinline__ void ffma2(unsigned long long& d,
                                             unsigned long long a,
                                             unsigned long long b) {
    asm volatile("fma.rn.f32x2 %0, %1, %2, %0;" : "+l"(d) : "l"(a), "l"(b));
}

// ---------------- init ----------------
__global__ void init_kernel()
{
    int i = blockIdx.x * 256 + threadIdx.x;
    if (i < 2 * BATCH * KC * PIX) g_h[i] = 0.0f;
    if (i < BATCH * KC * DCH)     g_vlad[i] = 0.0f;
    if (i < 16)                   g_barrier[i] = 0u;
}

// ---------------- transpose + tf32 split: X (n,c,p) -> Xt_hi/lo (j=n*196+p, c) ----------------
__global__ void __launch_bounds__(256) transpose_split(const float* __restrict__ X)
{
    __shared__ float ts[32][197];
    const int n = blockIdx.x, c0 = blockIdx.y * 32;
    for (int i = threadIdx.x; i < 32 * 196; i += 256) {
        int c = i / 196, p = i - c * 196;
        ts[c][p] = X[((size_t)n * CIN_ + c0 + c) * PIX + p];
    }
    __syncthreads();
    for (int i = threadIdx.x; i < 196 * 32; i += 256) {
        int p = i >> 5, c = i & 31;
        float v = ts[c][p];
        uint32_t hb; asm("cvt.rna.tf32.f32 %0, %1;" : "=r"(hb) : "f"(v));
        float hf = __uint_as_float(hb);
        size_t o = ((size_t)n * PIX + p) * CIN_ + c0 + c;
        g_xhi[o] = hf;
        g_xlo[o] = v - hf;
    }
}

// ---------------- weight tf32 split ----------------
__global__ void wsplit_kernel(const float* __restrict__ W)
{
    int i = blockIdx.x * 256 + threadIdx.x;
    if (i < DCH * CIN_) {
        float v = W[i];
        uint32_t hb; asm("cvt.rna.tf32.f32 %0, %1;" : "=r"(hb) : "f"(v));
        float hf = __uint_as_float(hb);
        g_whi[i] = hf;
        g_wlo[i] = v - hf;
    }
}

// ---------------- conv1: TF32x3 GEMM via mma.sync, 3-stage cp.async ring ----------------
// xrT[j, d] = bias[d] + sum_c x[j,c] * W[d,c]
// Block tile: 128 (j) x 128 (d), 8 warps as 2x4, warp tile 64x32.
// Pass 0 (64 iters): A = x_hi, B = {W_hi, W_lo}; Pass 1: A = x_lo, B = W_hi.
// SMEM (dynamic, 92160B): A[3][128][20] | B0[3][128][20] | B1[3][128][20]
#define C1_SMEM 92160
__global__ void __launch_bounds__(256)
conv1_mma(const float* __restrict__ bias)
{
    extern __shared__ char smc[];
    const uint32_t sbase = smem_to_u32(smc);
    const int tid  = threadIdx.x;
    const int wid  = tid >> 5, lane = tid & 31;
    const int d0   = blockIdx.x * 128;
    const int j0   = blockIdx.y * 128;
    const int wm   = wid & 1, wn = wid >> 1;
    const int g    = lane >> 2, tg = lane & 3;

    float c[4][4][4];
#pragma unroll
    for (int mt = 0; mt < 4; mt++)
#pragma unroll
        for (int nt = 0; nt < 4; nt++)
#pragma unroll
            for (int q = 0; q < 4; q++) c[mt][nt][q] = 0.0f;

    const int rr = tid >> 2, c4 = tid & 3;

    auto issue = [&](int i) {
        const int pass = i >> 6, kk = (i & 63) * 16, st = i % 3;
        const float* Asrc = pass ? g_xlo : g_xhi;
#pragma unroll
        for (int q = 0; q < 2; q++) {
            int r = rr + q * 64;
            uint32_t so = (uint32_t)(r * 80 + c4 * 16);
            size_t goA = (size_t)(j0 + r) * CIN_ + kk + c4 * 4;
            size_t goW = (size_t)(d0 + r) * CIN_ + kk + c4 * 4;
            cp16(sbase + st * 10240 + so,         Asrc + goA);
            cp16(sbase + 30720 + st * 10240 + so, g_whi + goW);
            if (pass == 0)
                cp16(sbase + 61440 + st * 10240 + so, g_wlo + goW);
        }
        CP_COMMIT();
    };

    issue(0); issue(1);
    for (int i = 0; i < 128; i++) {
        if (i < 126) CP_WAIT1(); else CP_WAIT0();
        __syncthreads();
        if (i + 2 < 128) issue(i + 2);

        const int st = i % 3, pass = i >> 6;
        const char* ab  = smc + st * 10240;
        const char* b0b = smc + 30720 + st * 10240;
        const char* b1b = smc + 61440 + st * 10240;

#pragma unroll
        for (int ks = 0; ks < 2; ks++) {
            const int kb = ks * 8 + tg;
            uint32_t a[4][4];
#pragma unroll
            for (int mt = 0; mt < 4; mt++) {
                int m = wm * 64 + mt * 16 + g;
                const float* pa0 = (const float*)(ab + m * 80);
                const float* pa1 = pa0 + 8 * 20;
                a[mt][0] = __float_as_uint(pa0[kb]);
                a[mt][1] = __float_as_uint(pa1[kb]);
                a[mt][2] = __float_as_uint(pa0[kb + 4]);
                a[mt][3] = __float_as_uint(pa1[kb + 4]);
            }
#pragma unroll
            for (int nt = 0; nt < 4; nt++) {
                int n = wn * 32 + nt * 8 + g;
                const float* pb = (const float*)(b0b + n * 80);
                uint32_t b0 = __float_as_uint(pb[kb]);
                uint32_t b1 = __float_as_uint(pb[kb + 4]);
#pragma unroll
                for (int mt = 0; mt < 4; mt++) MMA_TF32(c[mt][nt], a[mt], b0, b1);
                if (pass == 0) {
                    const float* pc = (const float*)(b1b + n * 80);
                    uint32_t e0 = __float_as_uint(pc[kb]);
                    uint32_t e1 = __float_as_uint(pc[kb + 4]);
#pragma unroll
                    for (int mt = 0; mt < 4; mt++) MMA_TF32(c[mt][nt], a[mt], e0, e1);
                }
            }
        }
    }

    // epilogue: add bias, store xrT[j][d] (float2)
#pragma unroll
    for (int mt = 0; mt < 4; mt++) {
        int r0 = j0 + wm * 64 + mt * 16 + g;
#pragma unroll
        for (int nt = 0; nt < 4; nt++) {
            int col = d0 + wn * 32 + nt * 8 + tg * 2;
            float2 bv = *(const float2*)&bias[col];
            float2 v0, v1;
            v0.x = c[mt][nt][0] + bv.x; v0.y = c[mt][nt][1] + bv.y;
            v1.x = c[mt][nt][2] + bv.x; v1.y = c[mt][nt][3] + bv.y;
            *(float2*)&g_xrt[(size_t)r0 * DCH + col]       = v0;
            *(float2*)&g_xrt[(size_t)(r0 + 8) * DCH + col] = v1;
        }
    }
}

// ---------------- conv2: FFMA GEMM on xrT -> wxb (n,k,p) ----------------
__global__ void __launch_bounds__(256)
conv2_db(const float* __restrict__ SW, const float* __restrict__ SB, float* __restrict__ out)
{
    constexpr int BK = 16, BN = 128, TM = 4, TN = 8;
    __shared__ __align__(16) float As[2][BK][64];
    __shared__ __align__(16) float Bs[2][BK][BN];
    __shared__ int obase[BN];

    const int tid = threadIdx.x;
    if (tid < BN) {
        int jg = blockIdx.x * BN + tid;
        int n = jg / PIX, p = jg - n * PIX;
        obase[tid] = n * KC * PIX + p;
    }
    __syncthreads();

    const int tx = tid & 15, ty = tid >> 4;
    const int bj = tid & 127, bk = tid >> 7;
    const int jg = blockIdx.x * BN + bj;

    float4 areg, brga, brgb;

    auto loadA = [&](int k0) {
        int r = tid >> 2, c4 = tid & 3;
        areg = *(const float4*)&SW[r * DCH + k0 + c4 * 4];
    };
    auto loadB = [&](int k0) {
        const float* src = &g_xrt[(size_t)jg * DCH + k0 + bk * 8];
        brga = *(const float4*)&src[0];
        brgb = *(const float4*)&src[4];
    };
    auto storeA = [&](int buf) {
        int r = tid >> 2, c4 = tid & 3;
        As[buf][c4 * 4 + 0][r] = areg.x;
        As[buf][c4 * 4 + 1][r] = areg.y;
        As[buf][c4 * 4 + 2][r] = areg.z;
        As[buf][c4 * 4 + 3][r] = areg.w;
    };
    auto storeB = [&](int buf) {
        Bs[buf][bk * 8 + 0][bj] = brga.x;
        Bs[buf][bk * 8 + 1][bj] = brga.y;
        Bs[buf][bk * 8 + 2][bj] = brga.z;
        Bs[buf][bk * 8 + 3][bj] = brga.w;
        Bs[buf][bk * 8 + 4][bj] = brgb.x;
        Bs[buf][bk * 8 + 5][bj] = brgb.y;
        Bs[buf][bk * 8 + 6][bj] = brgb.z;
        Bs[buf][bk * 8 + 7][bj] = brgb.w;
    };

    unsigned long long acc2[TM / 2][TN];
#pragma unroll
    for (int i = 0; i < TM / 2; i++)
#pragma unroll
        for (int j = 0; j < TN; j++) acc2[i][j] = 0ull;

    loadA(0); loadB(0);
    storeA(0); storeB(0);
    __syncthreads();

    int buf = 0;
    for (int k0 = 0; k0 < DCH; k0 += BK) {
        const bool more = (k0 + BK) < DCH;
        if (more) { loadA(k0 + BK); loadB(k0 + BK); }
#pragma unroll
        for (int kk = 0; kk < BK; kk++) {
            unsigned long long a2[TM / 2];
            ulonglong2 av = *(const ulonglong2*)&As[buf][kk][ty * TM];
            a2[0] = av.x; a2[1] = av.y;
            float4 b0 = *(const float4*)&Bs[buf][kk][tx * TN];
            float4 b1 = *(const float4*)&Bs[buf][kk][tx * TN + 4];
            unsigned long long bb[8];
            bb[0] = pack2(b0.x); bb[1] = pack2(b0.y); bb[2] = pack2(b0.z); bb[3] = pack2(b0.w);
            bb[4] = pack2(b1.x); bb[5] = pack2(b1.y); bb[6] = pack2(b1.z); bb[7] = pack2(b1.w);
#pragma unroll
            for (int i = 0; i < TM / 2; i++)
#pragma unroll
                for (int j = 0; j < TN; j++) ffma2(acc2[i][j], a2[i], bb[j]);
        }
        if (more) {
            storeA(buf ^ 1); storeB(buf ^ 1);
            __syncthreads();
            buf ^= 1;
        }
    }

#pragma unroll
    for (int i = 0; i < TM / 2; i++) {
        int d0 = ty * TM + 2 * i;
        float bv0 = SB[d0], bv1 = SB[d0 + 1];
#pragma unroll
        for (int j = 0; j < TN; j++) {
            unsigned long long u = acc2[i][j];
            float lo = __uint_as_float((unsigned)u);
            float hi = __uint_as_float((unsigned)(u >> 32));
            int o = obase[tx * TN + j];
            out[o + d0 * PIX]       = lo + bv0;
            out[o + (d0 + 1) * PIX] = hi + bv1;
        }
    }
}

// ---------------- persistent bidirectional GRU (896 threads, 4 ci-quarters) ----------------
#define GRU_THREADS 896
#define HS_FLOATS   (64 * 272)
#define WS_FLOATS   4608
#define PQ_FLOATS   1568
#define GRU_SMEM_FLOATS (HS_FLOATS + 3 * WS_FLOATS + 6 * PQ_FLOATS)

__global__ void __launch_bounds__(GRU_THREADS, 1)
gru_persistent(const float* __restrict__ Uz, const float* __restrict__ Ur,
               const float* __restrict__ Uh)
{
    extern __shared__ float sm[];
    float* hs = sm;                       // 17408
    float* wz = sm + HS_FLOATS;
    float* wr = wz + WS_FLOATS;
    float* wh = wr + WS_FLOATS;
    float* pz = wh + WS_FLOATS;           // 3*1568 partials (gate z / hcand)
    float* pr = pz + 3 * PQ_FLOATS;       // 3*1568 partials (gate r)

    const int blk = blockIdx.x;
    const int grp = blk >> 3;
    const int kg  = blk & 7;
    const int dir = grp >> 3;
    const int b   = grp & 7;
    const int tid = threadIdx.x;

    const int ko0 = kg * 8;
    for (int i = tid; i < WS_FLOATS; i += GRU_THREADS) {
        wz[i] = Uz[ko0 * 576 + i];
        wr[i] = Ur[ko0 * 576 + i];
        wh[i] = Uh[ko0 * 576 + i];
    }
    for (int i = tid; i < HS_FLOATS; i += GRU_THREADS) hs[i] = 0.0f;

    const int q     = tid / 224;          // ci-quarter 0..3
    const int lt    = tid - q * 224;
    const int ko_l  = lt / 28;
    const int g28   = lt - ko_l * 28;
    const int row   = g28 >> 1, xh = (g28 & 1) * 7;
    const int ko    = ko0 + ko_l;
    const int ci0   = q * 16;
    const int pbase = row * 14 + xh;
    const int pidx  = ko_l * PIX + pbase;

    float* hstate = g_h  + grp * KC * PIX;
    float* rhbuf  = g_rh + grp * KC * PIX;
    float* gdst   = (dir == 0) ? g_fwd : g_bwd;

    unsigned bar_target = 0;
    float zreg[7], hold[7];

    for (int s = 0; s < T_STEPS; s++) {
        const int t = dir ? (31 - s) : s;
        const int n = b * 32 + t;
        const float* wt = g_wxb + (n * KC + ko) * PIX + pbase;

        // ---- stage h (interior only) ----
        for (int i = tid; i < KC * PIX; i += GRU_THREADS) {
            int ci = i / PIX, p = i - ci * PIX;
            int y = p / 14, x = p - y * 14;
            hs[ci * 272 + (y + 1) * 17 + (x + 1)] = __ldcg(&hstate[i]);
        }
        __syncthreads();

        // ---- phase A: z,r convs over this quarter's 16 channels ----
        float az[7], ar[7];
#pragma unroll
        for (int i = 0; i < 7; i++) { az[i] = 0.0f; ar[i] = 0.0f; }
        {
            const float* wzb = wz + ko_l * 576 + ci0 * 9;
            const float* wrb = wr + ko_l * 576 + ci0 * 9;
            const float* hb  = hs + ci0 * 272 + row * 17 + xh;
#pragma unroll 1
            for (int ci = 0; ci < 16; ci++) {
                const float* hp = hb + ci * 272;
                float r0[9], r1[9], r2[9];
#pragma unroll
                for (int i = 0; i < 9; i++) { r0[i] = hp[i]; r1[i] = hp[17 + i]; r2[i] = hp[34 + i]; }
                const float* wz9 = wzb + ci * 9;
                const float* wr9 = wrb + ci * 9;
                float z0=wz9[0],z1=wz9[1],z2=wz9[2],z3=wz9[3],z4=wz9[4],z5=wz9[5],z6=wz9[6],z7=wz9[7],z8=wz9[8];
                float q0=wr9[0],q1=wr9[1],q2=wr9[2],q3=wr9[3],q4=wr9[4],q5=wr9[5],q6=wr9[6],q7=wr9[7],q8=wr9[8];
#pragma unroll
                for (int px = 0; px < 7; px++) {
                    az[px] += z0*r0[px] + z1*r0[px+1] + z2*r0[px+2]
                            + z3*r1[px] + z4*r1[px+1] + z5*r1[px+2]
                            + z6*r2[px] + z7*r2[px+1] + z8*r2[px+2];
                    ar[px] += q0*r0[px] + q1*r0[px+1] + q2*r0[px+2]
                            + q3*r1[px] + q4*r1[px+1] + q5*r1[px+2]
                            + q6*r2[px] + q7*r2[px+1] + q8*r2[px+2];
                }
            }
        }
        if (q > 0) {
            float* pzq = pz + (q - 1) * PQ_FLOATS;
            float* prq = pr + (q - 1) * PQ_FLOATS;
#pragma unroll
            for (int px = 0; px < 7; px++) { pzq[pidx + px] = az[px]; prq[pidx + px] = ar[px]; }
        }
        __syncthreads();
        if (q == 0) {
            const float* hko = hs + ko * 272 + (row + 1) * 17 + (xh + 1);
#pragma unroll
            for (int px = 0; px < 7; px++) {
                float w = wt[px];
                float zs = az[px] + pz[pidx + px] + pz[PQ_FLOATS + pidx + px] + pz[2 * PQ_FLOATS + pidx + px];
                float rs = ar[px] + pr[pidx + px] + pr[PQ_FLOATS + pidx + px] + pr[2 * PQ_FLOATS + pidx + px];
                float z = sigf(w + zs);
                float r = sigf(w + rs);
                float h0 = hko[px];
                zreg[px] = z;
                hold[px] = h0;
                rhbuf[ko * PIX + pbase + px] = r * h0;
            }
        }

        // ---- group barrier #1 ----
        __threadfence();
        __syncthreads();
        bar_target += 8;
        if (tid == 0) {
            atomicAdd(&g_barrier[grp], 1u);
            while (*((volatile unsigned int*)&g_barrier[grp]) < bar_target) __nanosleep(64);
            __threadfence();
        }
        __syncthreads();

        // ---- stage r*h ----
        for (int i = tid; i < KC * PIX; i += GRU_THREADS) {
            int ci = i / PIX, p = i - ci * PIX;
            int y = p / 14, x = p - y * 14;
            hs[ci * 272 + (y + 1) * 17 + (x + 1)] = __ldcg(&rhbuf[i]);
        }
        __syncthreads();

        // ---- phase B: h-candidate conv ----
        float ah[7];
#pragma unroll
        for (int i = 0; i < 7; i++) ah[i] = 0.0f;
        {
            const float* whb = wh + ko_l * 576 + ci0 * 9;
            const float* hb  = hs + ci0 * 272 + row * 17 + xh;
#pragma unroll 1
            for (int ci = 0; ci < 16; ci++) {
                const float* hp = hb + ci * 272;
                float r0[9], r1[9], r2[9];
#pragma unroll
                for (int i = 0; i < 9; i++) { r0[i] = hp[i]; r1[i] = hp[17 + i]; r2[i] = hp[34 + i]; }
                const float* w9 = whb + ci * 9;
                float w0=w9[0],w1=w9[1],w2=w9[2],w3=w9[3],w4=w9[4],w5=w9[5],w6=w9[6],w7=w9[7],w8=w9[8];
#pragma unroll
                for (int px = 0; px < 7; px++) {
                    ah[px] += w0*r0[px] + w1*r0[px+1] + w2*r0[px+2]
                            + w3*r1[px] + w4*r1[px+1] + w5*r1[px+2]
                            + w6*r2[px] + w7*r2[px+1] + w8*r2[px+2];
                }
            }
        }
        if (q > 0) {
            float* pzq = pz + (q - 1) * PQ_FLOATS;
#pragma unroll
            for (int px = 0; px < 7; px++) pzq[pidx + px] = ah[px];
        }
        __syncthreads();
        if (q == 0) {
            float* hdst = hstate + ko * PIX + pbase;
            float* fdst = gdst + (n * KC + ko) * PIX + pbase;
#pragma unroll
            for (int px = 0; px < 7; px++) {
                float hsum = ah[px] + pz[pidx + px] + pz[PQ_FLOATS + pidx + px] + pz[2 * PQ_FLOATS + pidx + px];
                float hh = tanhf(wt[px] + hsum);
                float z  = zreg[px];
                float hn = (1.0f - z) * hh + z * hold[px];
                hdst[px] = hn;
                fdst[px] = hn;
            }
        }

        // ---- group barrier #2 ----
        __threadfence();
        __syncthreads();
        bar_target += 8;
        if (tid == 0) {
            atomicAdd(&g_barrier[grp], 1u);
            while (*((volatile unsigned int*)&g_barrier[grp]) < bar_target) __nanosleep(64);
            __threadfence();
        }
        __syncthreads();
    }
}

// ---------------- softmax over K per pixel + per-(n,k) pixel sums ----------------
__global__ void softmax_kernel()
{
    const int n = blockIdx.x;
    const int p = threadIdx.x;
    const bool act = p < PIX;
    __shared__ float asum_s[KC];
    if (p < KC) asum_s[p] = 0.0f;
    __syncthreads();

    const float* f  = g_fwd + n * KC * PIX + p;
    const float* bd = g_bwd + n * KC * PIX + p;
    float m = -1e30f;
    if (act) {
        for (int k = 0; k < KC; k++) m = fmaxf(m, f[k * PIX] + bd[k * PIX]);
    }
    float ssum = 0.0f;
    if (act) {
        for (int k = 0; k < KC; k++) ssum += expf(f[k * PIX] + bd[k * PIX] - m);
    }
    const float inv = act ? (1.0f / ssum) : 0.0f;
    float* A = g_assign + n * KC * PIX + p;
    for (int k = 0; k < KC; k++) {
        float e = act ? expf(f[k * PIX] + bd[k * PIX] - m) * inv : 0.0f;
        if (act) A[k * PIX] = e;
        float es = e;
#pragma unroll
        for (int off = 16; off; off >>= 1) es += __shfl_down_sync(0xffffffffu, es, off);
        if ((p & 31) == 0) atomicAdd(&asum_s[k], es);
    }
    __syncthreads();
    if (p < KC) g_asum[n * KC + p] = asum_s[p];
}

// ---------------- VLAD einsum (B side reads xrT) ----------------
__global__ void vlad_gemm_kernel()
{
    __shared__ float As[14][65];
    __shared__ float Bs[14][65];
    const int b = blockIdx.y, d0 = blockIdx.x * 64, ch = blockIdx.z;
    const int tid = threadIdx.x;
    const int tx = tid & 15, ty = tid >> 4;

    float acc[4][4];
#pragma unroll
    for (int i = 0; i < 4; i++)
#pragma unroll
        for (int j = 0; j < 4; j++) acc[i][j] = 0.0f;

    for (int f = 0; f < 4; f++) {
        int n = b * 32 + ch * 4 + f;
        const float* Ap = g_assign + n * KC * PIX;
        const float* Xp = g_xrt + (size_t)n * PIX * DCH;
        for (int p0 = 0; p0 < PIX; p0 += 14) {
            for (int i = tid; i < 896; i += 256) {
                int r = i / 14, pp = i - r * 14;
                As[pp][r] = Ap[r * PIX + p0 + pp];
            }
            for (int i = tid; i < 896; i += 256) {
                int pp = i >> 6, r = i & 63;
                Bs[pp][r] = Xp[(size_t)(p0 + pp) * DCH + d0 + r];
            }
            __syncthreads();
#pragma unroll
            for (int pp = 0; pp < 14; pp++) {
                float a[4], x[4];
#pragma unroll
                for (int i = 0; i < 4; i++) a[i] = As[pp][ty * 4 + i];
#pragma unroll
                for (int j = 0; j < 4; j++) x[j] = Bs[pp][tx * 4 + j];
#pragma unroll
                for (int i = 0; i < 4; i++)
#pragma unroll
                    for (int j = 0; j < 4; j++) acc[i][j] += a[i] * x[j];
            }
            __syncthreads();
        }
    }
#pragma unroll
    for (int i = 0; i < 4; i++)
#pragma unroll
        for (int j = 0; j < 4; j++)
            atomicAdd(&g_vlad[(b * KC + ty * 4 + i) * DCH + d0 + tx * 4 + j], acc[i][j]);
}

// ---------------- subtract a-term + intra-row L2 normalize ----------------
__global__ void rownorm_kernel(const float* __restrict__ centers, float* __restrict__ out)
{
    const int k = blockIdx.x, b = blockIdx.y;
    const int tid = threadIdx.x;
    __shared__ float sred[128];
    __shared__ float s_sh;

    if (tid < 32) {
        float s = g_asum[(b * 32 + tid) * KC + k];
#pragma unroll
        for (int off = 16; off; off >>= 1) s += __shfl_down_sync(0xffffffffu, s, off);
        if (tid == 0) s_sh = s;
    }
    __syncthreads();
    const float s = s_sh;

    float v[4];
    float ssq = 0.0f;
#pragma unroll
    for (int j = 0; j < 4; j++) {
        int d = j * 128 + tid;
        v[j] = g_vlad[(b * KC + k) * DCH + d] - s * centers[k * DCH + d];
        ssq += v[j] * v[j];
    }
    sred[tid] = ssq;
    __syncthreads();
    for (int off = 64; off; off >>= 1) {
        if (tid < off) sred[tid] += sred[tid + off];
        __syncthreads();
    }
    const float scale = 1.0f / fmaxf(sqrtf(sred[0]), 1e-12f);
#pragma unroll
    for (int j = 0; j < 4; j++)
        out[b * KC * DCH + k * DCH + j * 128 + tid] = v[j] * scale;
}

// ---------------- final per-batch L2 normalize ----------------
__global__ void bnorm_kernel(float* __restrict__ out)
{
    const int b = blockIdx.x;
    const int tid = threadIdx.x;
    __shared__ float sred[256];
    float* o = out + b * KC * DCH;
    float ssq = 0.0f;
    for (int i = tid; i < KC * DCH; i += 256) { float v = o[i]; ssq += v * v; }
    sred[tid] = ssq;
    __syncthreads();
    for (int off = 128; off; off >>= 1) {
        if (tid < off) sred[tid] += sred[tid + off];
        __syncthreads();
    }
    const float scale = 1.0f / fmaxf(sqrtf(sred[0]), 1e-12f);
    for (int i = tid; i < KC * DCH; i += 256) o[i] *= scale;
}

// ---------------- host launcher ----------------
extern "C" void kernel_launch(void* const* d_in, const int* in_sizes, int n_in,
                              void* d_out, int out_size)
{
    const float* x       = (const float*)d_in[0];
    const float* redu_w  = (const float*)d_in[1];
    const float* redu_b  = (const float*)d_in[2];
    const float* share_w = (const float*)d_in[3];
    const float* share_b = (const float*)d_in[4];
    const float* U_z     = (const float*)d_in[5];
    const float* U_r     = (const float*)d_in[6];
    const float* U_h     = (const float*)d_in[7];
    const float* centers = (const float*)d_in[8];
    float* out = (float*)d_out;

    const int GRU_SMEM = GRU_SMEM_FLOATS * 4;   // ~162.5 KB
    cudaFuncSetAttribute(gru_persistent, cudaFuncAttributeMaxDynamicSharedMemorySize, GRU_SMEM);
    cudaFuncSetAttribute(conv1_mma, cudaFuncAttributeMaxDynamicSharedMemorySize, C1_SMEM);

    void* wxb_p; cudaGetSymbolAddress(&wxb_p, g_wxb);

    init_kernel<<<1024, 256>>>();

    // transpose + tf32 split of x, and of redu_w
    transpose_split<<<dim3(NT, CIN_ / 32), 256>>>(x);
    wsplit_kernel<<<(DCH * CIN_ + 255) / 256, 256>>>(redu_w);

    // conv1: TF32x3 GEMM via mma.sync (3-stage ring) -> xrT (j, d)
    conv1_mma<<<dim3(DCH / 128, NJ / 128), 256, C1_SMEM>>>(redu_b);

    // conv2: FFMA GEMM (64 x 512) on xrT -> wxb (n,k,p)
    conv2_db<<<NJ / 128, 256>>>(share_w, share_b, (float*)wxb_p);

    // persistent bidirectional GRU (896 threads, 4 ci-quarters)
    gru_persistent<<<128, GRU_THREADS, GRU_SMEM>>>(U_z, U_r, U_h);

    softmax_kernel<<<NT, 224>>>();
    vlad_gemm_kernel<<<dim3(8, BATCH, 8), 256>>>();
    rownorm_kernel<<<dim3(KC, BATCH), 128>>>(centers, out);
    bnorm_kernel<<<BATCH, 256>>>(out);
}

// round 10
// speedup vs baseline: 1.2425x; 1.2256x over previous
#include <cuda_runtime.h>
#include <cstdint>

#define T_STEPS 32
#define BATCH   8
#define NT      256
#define CIN_    1024
#define DCH     512
#define KC      64
#define PIX     196

typedef unsigned long long ull;

// ---------------- scratch (device globals; no allocations) ----------------
__device__ float g_xr[NT * DCH * PIX];       // (n, d, p)
__device__ float g_wxb[NT * KC * PIX];       // (n, k, p)
__device__ float g_h[2 * BATCH * KC * PIX];  // per-direction hidden state
__device__ float g_rh[2 * BATCH * KC * PIX];
__device__ float g_fwd[NT * KC * PIX];
__device__ float g_bwd[NT * KC * PIX];
__device__ float g_assign[NT * KC * PIX];
__device__ float g_asum[NT * KC];
__device__ float g_vlad[BATCH * KC * DCH];
__device__ unsigned int g_barrier[16];

static __device__ __forceinline__ float sigf(float v) { return 1.0f / (1.0f + expf(-v)); }

// packed fp32x2 helpers
static __device__ __forceinline__ ull pack2(float v) {
    ull r;
    unsigned u = __float_as_uint(v);
    asm("mov.b64 %0, {%1, %1};" : "=l"(r) : "r"(u));
    return r;
}
static __device__ __forceinline__ void ffma2(ull& d, ull a, ull b) {
    asm volatile("fma.rn.f32x2 %0, %1, %2, %0;" : "+l"(d) : "l"(a), "l"(b));
}
static __device__ __forceinline__ float lo32(ull u) { return __uint_as_float((unsigned)u); }
static __device__ __forceinline__ float hi32(ull u) { return __uint_as_float((unsigned)(u >> 32)); }

// ---------------- init: zero hidden states + vlad + barriers ----------------
__global__ void init_kernel()
{
    int i = blockIdx.x * 256 + threadIdx.x;
    if (i < 2 * BATCH * KC * PIX) g_h[i] = 0.0f;
    if (i < BATCH * KC * DCH)     g_vlad[i] = 0.0f;
    if (i < 16)                   g_barrier[i] = 0u;
}

// ---------------- 1x1 conv as double-buffered tiled SGEMM (f32x2 FMAs) ----------------
// out[(n*OC + d)*196 + p] = bias[d] + sum_c W[d][c] * X[(n*CIN + c)*196 + p]
template<int BM, int TM, int CIN, int OC>
__global__ void __launch_bounds__(256)
conv1x1_db(const float* __restrict__ X, const float* __restrict__ W,
           const float* __restrict__ bias, float* __restrict__ out)
{
    constexpr int BK = 16, BN = 128, TN = 8;
    constexpr int AL4 = (BM * BK) / (4 * 256);
    __shared__ __align__(16) float As[2][BK][BM];
    __shared__ __align__(16) float Bs[2][BK][BN];
    __shared__ int cbase[BN], obase[BN];

    const int tid = threadIdx.x;
    if (tid < BN) {
        int jg = blockIdx.x * BN + tid;
        int n = jg / PIX, p = jg - n * PIX;
        cbase[tid] = n * CIN * PIX + p;
        obase[tid] = n * OC * PIX + p;
    }
    __syncthreads();

    const int m0 = blockIdx.y * BM;
    const int tx = tid & 15, ty = tid >> 4;
    const int bj = tid & 127, bk = tid >> 7;
    const int cb = cbase[bj];

    float4 areg[AL4];
    float  breg[8];

    auto loadA = [&](int k0) {
#pragma unroll
        for (int i = 0; i < AL4; i++) {
            int idx = tid + i * 256;
            int r = idx >> 2, c4 = idx & 3;
            areg[i] = *(const float4*)&W[(m0 + r) * CIN + k0 + c4 * 4];
        }
    };
    auto loadB = [&](int k0) {
#pragma unroll
        for (int i = 0; i < 8; i++) breg[i] = X[cb + (k0 + bk * 8 + i) * PIX];
    };
    auto storeA = [&](int buf) {
#pragma unroll
        for (int i = 0; i < AL4; i++) {
            int idx = tid + i * 256;
            int r = idx >> 2, c4 = idx & 3;
            As[buf][c4 * 4 + 0][r] = areg[i].x;
            As[buf][c4 * 4 + 1][r] = areg[i].y;
            As[buf][c4 * 4 + 2][r] = areg[i].z;
            As[buf][c4 * 4 + 3][r] = areg[i].w;
        }
    };
    auto storeB = [&](int buf) {
#pragma unroll
        for (int i = 0; i < 8; i++) Bs[buf][bk * 8 + i][bj] = breg[i];
    };

    ull acc2[TM / 2][TN];
#pragma unroll
    for (int i = 0; i < TM / 2; i++)
#pragma unroll
        for (int j = 0; j < TN; j++) acc2[i][j] = 0ull;

    loadA(0); loadB(0);
    storeA(0); storeB(0);
    __syncthreads();

    int buf = 0;
    for (int k0 = 0; k0 < CIN; k0 += BK) {
        const bool more = (k0 + BK) < CIN;
        if (more) { loadA(k0 + BK); loadB(k0 + BK); }
#pragma unroll
        for (int kk = 0; kk < BK; kk++) {
            ull a2[TM / 2];
#pragma unroll
            for (int i = 0; i < TM / 2; i += 2) {
                ulonglong2 av = *(const ulonglong2*)&As[buf][kk][ty * TM + i * 2];
                a2[i] = av.x; a2[i + 1] = av.y;
            }
            float4 b0 = *(const float4*)&Bs[buf][kk][tx * TN];
            float4 b1 = *(const float4*)&Bs[buf][kk][tx * TN + 4];
            ull bb[8];
            bb[0] = pack2(b0.x); bb[1] = pack2(b0.y); bb[2] = pack2(b0.z); bb[3] = pack2(b0.w);
            bb[4] = pack2(b1.x); bb[5] = pack2(b1.y); bb[6] = pack2(b1.z); bb[7] = pack2(b1.w);
#pragma unroll
            for (int i = 0; i < TM / 2; i++)
#pragma unroll
                for (int j = 0; j < TN; j++) ffma2(acc2[i][j], a2[i], bb[j]);
        }
        if (more) {
            storeA(buf ^ 1); storeB(buf ^ 1);
            __syncthreads();
            buf ^= 1;
        }
    }

#pragma unroll
    for (int i = 0; i < TM / 2; i++) {
        int d0 = m0 + ty * TM + 2 * i;
        float bv0 = bias[d0], bv1 = bias[d0 + 1];
#pragma unroll
        for (int j = 0; j < TN; j++) {
            ull u = acc2[i][j];
            int o = obase[tx * TN + j];
            out[o + d0 * PIX]       = lo32(u) + bv0;
            out[o + (d0 + 1) * PIX] = hi32(u) + bv1;
        }
    }
}

// ---------------- persistent bidirectional GRU (packed f32x2 conv) ----------------
// 448 threads = 4 ci-quarters x 8 ko x 14 rows; each thread: one 14-px output row.
// Padded image: 16 rows x stride 18 per channel (halo cols 0,15; rows 0,15 zero).
#define GRU_THREADS 448
#define HS_STRIDE   288                    // 16 * 18
#define HS_FLOATS   (64 * HS_STRIDE)       // 18432
#define WS_FLOATS   4608
#define PQ_FLOATS   1568
#define GRU_SMEM_FLOATS (HS_FLOATS + 3 * WS_FLOATS + 6 * PQ_FLOATS)

__global__ void __launch_bounds__(GRU_THREADS, 1)
gru_persistent(const float* __restrict__ Uz, const float* __restrict__ Ur,
               const float* __restrict__ Uh)
{
    extern __shared__ float sm[];
    float* hs = sm;                        // 64 channels, 16x18 padded
    float* wz = sm + HS_FLOATS;
    float* wr = wz + WS_FLOATS;
    float* wh = wr + WS_FLOATS;
    float* pz = wh + WS_FLOATS;            // 3*1568 partials (z / hcand)
    float* pr = pz + 3 * PQ_FLOATS;        // 3*1568 partials (r)

    const int blk = blockIdx.x;
    const int grp = blk >> 3;              // dir*8 + b
    const int kg  = blk & 7;
    const int dir = grp >> 3;
    const int b   = grp & 7;
    const int tid = threadIdx.x;

    const int ko0 = kg * 8;
    for (int i = tid; i < WS_FLOATS; i += GRU_THREADS) {
        wz[i] = Uz[ko0 * 576 + i];
        wr[i] = Ur[ko0 * 576 + i];
        wh[i] = Uh[ko0 * 576 + i];
    }
    for (int i = tid; i < HS_FLOATS; i += GRU_THREADS) hs[i] = 0.0f;
    __syncthreads();

    const int q     = tid / 112;           // ci-quarter 0..3
    const int lt    = tid - q * 112;
    const int ko_l  = lt / 14;             // 0..7
    const int row   = lt - ko_l * 14;      // 0..13
    const int ko    = ko0 + ko_l;
    const int ci0   = q * 16;
    const int pidx  = ko_l * PIX + row * 14;

    float* hstate = g_h  + grp * KC * PIX;
    float* rhbuf  = g_rh + grp * KC * PIX;
    float* gdst   = (dir == 0) ? g_fwd : g_bwd;

    unsigned bar_target = 0;
    float zreg[14], hold[14];

    for (int s = 0; s < T_STEPS; s++) {
        const int t = dir ? (31 - s) : s;
        const int n = b * 32 + t;
        const float* wt = g_wxb + (n * KC + ko) * PIX + row * 14;

        // ---- stage h (interior only; halo stays 0) ----
        for (int i = tid; i < KC * PIX; i += GRU_THREADS) {
            int ci = i / PIX, p = i - ci * PIX;
            int y = p / 14, x = p - y * 14;
            hs[ci * HS_STRIDE + (y + 1) * 18 + (x + 1)] = __ldcg(&hstate[i]);
        }
        __syncthreads();

        // ---- phase A: z,r convs over this quarter's 16 channels (packed px pairs) ----
        ull az2[7], ar2[7];
#pragma unroll
        for (int j = 0; j < 7; j++) { az2[j] = 0ull; ar2[j] = 0ull; }
        {
            const float* wzb = wz + ko_l * 576 + ci0 * 9;
            const float* wrb = wr + ko_l * 576 + ci0 * 9;
            const float* hbase = hs + ci0 * HS_STRIDE + row * 18;
#pragma unroll 1
            for (int ci = 0; ci < 16; ci++) {
                const float* hrow = hbase + ci * HS_STRIDE;
                const float* wz9 = wzb + ci * 9;
                const float* wr9 = wrb + ci * 9;
#pragma unroll
                for (int r = 0; r < 3; r++) {
                    ull p[8];
#pragma unroll
                    for (int k = 0; k < 8; k++)
                        p[k] = *(const ull*)(hrow + r * 18 + 2 * k);
                    ull wa0 = pack2(wz9[3 * r + 0]);
                    ull wa1 = pack2(wz9[3 * r + 1]);
                    ull wa2 = pack2(wz9[3 * r + 2]);
                    ull wb0 = pack2(wr9[3 * r + 0]);
                    ull wb1 = pack2(wr9[3 * r + 1]);
                    ull wb2 = pack2(wr9[3 * r + 2]);
#pragma unroll
                    for (int j = 0; j < 7; j++) {
                        ull sft = (p[j] >> 32) | (p[j + 1] << 32);
                        ffma2(az2[j], p[j],     wa0);
                        ffma2(az2[j], sft,      wa1);
                        ffma2(az2[j], p[j + 1], wa2);
                        ffma2(ar2[j], p[j],     wb0);
                        ffma2(ar2[j], sft,      wb1);
                        ffma2(ar2[j], p[j + 1], wb2);
                    }
                }
            }
        }
        if (q > 0) {
            ull* pzq = (ull*)(pz + (q - 1) * PQ_FLOATS + pidx);
            ull* prq = (ull*)(pr + (q - 1) * PQ_FLOATS + pidx);
#pragma unroll
            for (int j = 0; j < 7; j++) { pzq[j] = az2[j]; prq[j] = ar2[j]; }
        }
        __syncthreads();
        if (q == 0) {
            float az[14], ar[14];
#pragma unroll
            for (int j = 0; j < 7; j++) {
                az[2 * j] = lo32(az2[j]); az[2 * j + 1] = hi32(az2[j]);
                ar[2 * j] = lo32(ar2[j]); ar[2 * j + 1] = hi32(ar2[j]);
            }
#pragma unroll
            for (int qq = 0; qq < 3; qq++) {
                const float* pzq = pz + qq * PQ_FLOATS + pidx;
                const float* prq = pr + qq * PQ_FLOATS + pidx;
#pragma unroll
                for (int px = 0; px < 14; px++) { az[px] += pzq[px]; ar[px] += prq[px]; }
            }
            const float* hko = hs + ko * HS_STRIDE + (row + 1) * 18 + 1;
            float* rdst = rhbuf + ko * PIX + row * 14;
#pragma unroll
            for (int px = 0; px < 14; px++) {
                float w = wt[px];
                float z = sigf(w + az[px]);
                float r = sigf(w + ar[px]);
                float h0 = hko[px];
                zreg[px] = z;
                hold[px] = h0;
                rdst[px] = r * h0;
            }
        }

        // ---- group barrier #1 ----
        __threadfence();
        __syncthreads();
        bar_target += 8;
        if (tid == 0) {
            atomicAdd(&g_barrier[grp], 1u);
            while (*((volatile unsigned int*)&g_barrier[grp]) < bar_target) __nanosleep(64);
            __threadfence();
        }
        __syncthreads();

        // ---- stage r*h ----
        for (int i = tid; i < KC * PIX; i += GRU_THREADS) {
            int ci = i / PIX, p = i - ci * PIX;
            int y = p / 14, x = p - y * 14;
            hs[ci * HS_STRIDE + (y + 1) * 18 + (x + 1)] = __ldcg(&rhbuf[i]);
        }
        __syncthreads();

        // ---- phase B: h-candidate conv ----
        ull ah2[7];
#pragma unroll
        for (int j = 0; j < 7; j++) ah2[j] = 0ull;
        {
            const float* whb = wh + ko_l * 576 + ci0 * 9;
            const float* hbase = hs + ci0 * HS_STRIDE + row * 18;
#pragma unroll 1
            for (int ci = 0; ci < 16; ci++) {
                const float* hrow = hbase + ci * HS_STRIDE;
                const float* w9 = whb + ci * 9;
#pragma unroll
                for (int r = 0; r < 3; r++) {
                    ull p[8];
#pragma unroll
                    for (int k = 0; k < 8; k++)
                        p[k] = *(const ull*)(hrow + r * 18 + 2 * k);
                    ull wa0 = pack2(w9[3 * r + 0]);
                    ull wa1 = pack2(w9[3 * r + 1]);
                    ull wa2 = pack2(w9[3 * r + 2]);
#pragma unroll
                    for (int j = 0; j < 7; j++) {
                        ull sft = (p[j] >> 32) | (p[j + 1] << 32);
                        ffma2(ah2[j], p[j],     wa0);
                        ffma2(ah2[j], sft,      wa1);
                        ffma2(ah2[j], p[j + 1], wa2);
                    }
                }
            }
        }
        if (q > 0) {
            ull* pzq = (ull*)(pz + (q - 1) * PQ_FLOATS + pidx);
#pragma unroll
            for (int j = 0; j < 7; j++) pzq[j] = ah2[j];
        }
        __syncthreads();
        if (q == 0) {
            float ah[14];
#pragma unroll
            for (int j = 0; j < 7; j++) {
                ah[2 * j] = lo32(ah2[j]); ah[2 * j + 1] = hi32(ah2[j]);
            }
#pragma unroll
            for (int qq = 0; qq < 3; qq++) {
                const float* pzq = pz + qq * PQ_FLOATS + pidx;
#pragma unroll
                for (int px = 0; px < 14; px++) ah[px] += pzq[px];
            }
            float* hdst = hstate + ko * PIX + row * 14;
            float* fdst = gdst + (n * KC + ko) * PIX + row * 14;
#pragma unroll
            for (int px = 0; px < 14; px++) {
                float hh = tanhf(wt[px] + ah[px]);
                float z  = zreg[px];
                float hn = (1.0f - z) * hh + z * hold[px];
                hdst[px] = hn;
                fdst[px] = hn;
            }
        }

        // ---- group barrier #2 ----
        __threadfence();
        __syncthreads();
        bar_target += 8;
        if (tid == 0) {
            atomicAdd(&g_barrier[grp], 1u);
            while (*((volatile unsigned int*)&g_barrier[grp]) < bar_target) __nanosleep(64);
            __threadfence();
        }
        __syncthreads();
    }
}

// ---------------- softmax over K per pixel + per-(n,k) pixel sums ----------------
__global__ void softmax_kernel()
{
    const int n = blockIdx.x;
    const int p = threadIdx.x;   // 224 threads, 196 active
    const bool act = p < PIX;
    __shared__ float asum_s[KC];
    if (p < KC) asum_s[p] = 0.0f;
    __syncthreads();

    const float* f  = g_fwd + n * KC * PIX + p;
    const float* bd = g_bwd + n * KC * PIX + p;
    float m = -1e30f;
    if (act) {
        for (int k = 0; k < KC; k++) m = fmaxf(m, f[k * PIX] + bd[k * PIX]);
    }
    float ssum = 0.0f;
    if (act) {
        for (int k = 0; k < KC; k++) ssum += expf(f[k * PIX] + bd[k * PIX] - m);
    }
    const float inv = act ? (1.0f / ssum) : 0.0f;
    float* A = g_assign + n * KC * PIX + p;
    for (int k = 0; k < KC; k++) {
        float e = act ? expf(f[k * PIX] + bd[k * PIX] - m) * inv : 0.0f;
        if (act) A[k * PIX] = e;
        float es = e;
#pragma unroll
        for (int off = 16; off; off >>= 1) es += __shfl_down_sync(0xffffffffu, es, off);
        if ((p & 31) == 0) atomicAdd(&asum_s[k], es);
    }
    __syncthreads();
    if (p < KC) g_asum[n * KC + p] = asum_s[p];
}

// ---------------- VLAD einsum: vlad[b,k,d] += sum_{t,p} assign * xr ----------------
__global__ void vlad_gemm_kernel()
{
    __shared__ float As[14][65];
    __shared__ float Bs[14][65];
    const int b = blockIdx.y, d0 = blockIdx.x * 64, ch = blockIdx.z;
    const int tid = threadIdx.x;
    const int tx = tid & 15, ty = tid >> 4;

    float acc[4][4];
#pragma unroll
    for (int i = 0; i < 4; i++)
#pragma unroll
        for (int j = 0; j < 4; j++) acc[i][j] = 0.0f;

    for (int f = 0; f < 4; f++) {
        int n = b * 32 + ch * 4 + f;
        const float* Ap = g_assign + n * KC * PIX;
        const float* Xp = g_xr + (size_t)n * DCH * PIX;
        for (int p0 = 0; p0 < PIX; p0 += 14) {
            for (int i = tid; i < 896; i += 256) {
                int r = i / 14, pp = i - r * 14;
                As[pp][r] = Ap[r * PIX + p0 + pp];
                Bs[pp][r] = Xp[(d0 + r) * PIX + p0 + pp];
            }
            __syncthreads();
#pragma unroll
            for (int pp = 0; pp < 14; pp++) {
                float a[4], x[4];
#pragma unroll
                for (int i = 0; i < 4; i++) a[i] = As[pp][ty * 4 + i];
#pragma unroll
                for (int j = 0; j < 4; j++) x[j] = Bs[pp][tx * 4 + j];
#pragma unroll
                for (int i = 0; i < 4; i++)
#pragma unroll
                    for (int j = 0; j < 4; j++) acc[i][j] += a[i] * x[j];
            }
            __syncthreads();
        }
    }
#pragma unroll
    for (int i = 0; i < 4; i++)
#pragma unroll
        for (int j = 0; j < 4; j++)
            atomicAdd(&g_vlad[(b * KC + ty * 4 + i) * DCH + d0 + tx * 4 + j], acc[i][j]);
}

// ---------------- subtract a-term + intra-row L2 normalize ----------------
__global__ void rownorm_kernel(const float* __restrict__ centers, float* __restrict__ out)
{
    const int k = blockIdx.x, b = blockIdx.y;
    const int tid = threadIdx.x;  // 128
    __shared__ float sred[128];
    __shared__ float s_sh;

    if (tid < 32) {
        float s = g_asum[(b * 32 + tid) * KC + k];
#pragma unroll
        for (int off = 16; off; off >>= 1) s += __shfl_down_sync(0xffffffffu, s, off);
        if (tid == 0) s_sh = s;
    }
    __syncthreads();
    const float s = s_sh;

    float v[4];
    float ssq = 0.0f;
#pragma unroll
    for (int j = 0; j < 4; j++) {
        int d = j * 128 + tid;
        v[j] = g_vlad[(b * KC + k) * DCH + d] - s * centers[k * DCH + d];
        ssq += v[j] * v[j];
    }
    sred[tid] = ssq;
    __syncthreads();
    for (int off = 64; off; off >>= 1) {
        if (tid < off) sred[tid] += sred[tid + off];
        __syncthreads();
    }
    const float scale = 1.0f / fmaxf(sqrtf(sred[0]), 1e-12f);
#pragma unroll
    for (int j = 0; j < 4; j++)
        out[b * KC * DCH + k * DCH + j * 128 + tid] = v[j] * scale;
}

// ---------------- final per-batch L2 normalize ----------------
__global__ void bnorm_kernel(float* __restrict__ out)
{
    const int b = blockIdx.x;
    const int tid = threadIdx.x; // 256
    __shared__ float sred[256];
    float* o = out + b * KC * DCH;
    float ssq = 0.0f;
    for (int i = tid; i < KC * DCH; i += 256) { float v = o[i]; ssq += v * v; }
    sred[tid] = ssq;
    __syncthreads();
    for (int off = 128; off; off >>= 1) {
        if (tid < off) sred[tid] += sred[tid + off];
        __syncthreads();
    }
    const float scale = 1.0f / fmaxf(sqrtf(sred[0]), 1e-12f);
    for (int i = tid; i < KC * DCH; i += 256) o[i] *= scale;
}

// ---------------- host launcher ----------------
extern "C" void kernel_launch(void* const* d_in, const int* in_sizes, int n_in,
                              void* d_out, int out_size)
{
    const float* x       = (const float*)d_in[0];
    const float* redu_w  = (const float*)d_in[1];
    const float* redu_b  = (const float*)d_in[2];
    const float* share_w = (const float*)d_in[3];
    const float* share_b = (const float*)d_in[4];
    const float* U_z     = (const float*)d_in[5];
    const float* U_r     = (const float*)d_in[6];
    const float* U_h     = (const float*)d_in[7];
    const float* centers = (const float*)d_in[8];
    float* out = (float*)d_out;

    const int GRU_SMEM = GRU_SMEM_FLOATS * 4;   // ~162.8 KB
    cudaFuncSetAttribute(gru_persistent, cudaFuncAttributeMaxDynamicSharedMemorySize, GRU_SMEM);

    void* xr_p;  cudaGetSymbolAddress(&xr_p,  g_xr);
    void* wxb_p; cudaGetSymbolAddress(&wxb_p, g_wxb);

    init_kernel<<<1024, 256>>>();

    // xr = 1x1 reduce conv + bias : GEMM (512 x 1024) @ (1024 x 50176)
    conv1x1_db<128, 8, CIN_, DCH>
        <<<dim3(50176 / 128, DCH / 128), 256>>>(x, redu_w, redu_b, (float*)xr_p);

    // wxb = 1x1 share conv + bias : GEMM (64 x 512) @ (512 x 50176)
    conv1x1_db<64, 4, DCH, KC>
        <<<dim3(50176 / 128, 1), 256>>>((const float*)xr_p, share_w, share_b, (float*)wxb_p);

    // persistent bidirectional GRU (packed f32x2, 448 threads)
    gru_persistent<<<128, GRU_THREADS, GRU_SMEM>>>(U_z, U_r, U_h);

    softmax_kernel<<<NT, 224>>>();
    vlad_gemm_kernel<<<dim3(8, BATCH, 8), 256>>>();
    rownorm_kernel<<<dim3(KC, BATCH), 128>>>(centers, out);
    bnorm_kernel<<<BATCH, 256>>>(out);
}